// round 1
// baseline (speedup 1.0000x reference)
#include <cuda_runtime.h>
#include <math.h>

// ZBLRepulsion: E = 0.5*rs*KE * sum_edges [ Zi*Zj/dr * f(dist) * cos_cutoff(dr) ]
// Inputs (metadata order):
//  0: R        [100000,3] f32
//  1: Z        [100000]   i32
//  2: idx      [2, 6400000] i32   (idx_i = idx[0,:], idx_j = idx[1,:])
//  3: box      [3] f32            (unused)
//  4: offsets  [E,3] f32          (unused)
//  5: a_exp    [1] f32  (inv-softplus space)
//  6: a_num    [1] f32
//  7: coefficients [4] f32
//  8: exponents    [4] f32
//  9: rep_scale    [1] f32
// out: scalar f32

#define N_ATOMS_MAX 100000
#define KE_CONST 14.3996f
#define R_MAX_F 6.0f

// Padded atom record: x, y, z, float(Z). One aligned LDG.128 per gather.
__device__ float4 g_Rp[N_ATOMS_MAX];
// pow table: g_tab[z] = z ^ softplus(a_exp), z in [0, 63]
__device__ float  g_tab[64];
// params: [0..3]=softplus(coeff), [4..7]=softplus(exp), [8]=1/softplus(a_num),
//         [9]=0.5*KE*softplus(rep_scale)
__device__ float  g_par[10];

__device__ __forceinline__ float softplus_f(float x) {
    // stable for the small magnitudes used here
    return log1pf(expf(x));
}

__global__ void prologue_kernel(const float* __restrict__ R,
                                const int*   __restrict__ Z,
                                const float* __restrict__ a_exp,
                                const float* __restrict__ a_num,
                                const float* __restrict__ coef,
                                const float* __restrict__ expo,
                                const float* __restrict__ rep_scale,
                                float* __restrict__ out,
                                int n_atoms) {
    int t = blockIdx.x * blockDim.x + threadIdx.x;
    if (t < n_atoms) {
        float x = R[3 * t + 0];
        float y = R[3 * t + 1];
        float z = R[3 * t + 2];
        g_Rp[t] = make_float4(x, y, z, (float)Z[t]);
    }
    if (blockIdx.x == 0 && threadIdx.x < 64) {
        float ae = softplus_f(a_exp[0]);
        g_tab[threadIdx.x] = powf((float)threadIdx.x, ae);
        if (threadIdx.x < 4) {
            g_par[threadIdx.x]     = softplus_f(coef[threadIdx.x]);
            g_par[4 + threadIdx.x] = softplus_f(expo[threadIdx.x]);
        }
        if (threadIdx.x == 0) {
            g_par[8] = 1.0f / softplus_f(a_num[0]);
            g_par[9] = 0.5f * KE_CONST * softplus_f(rep_scale[0]);
            out[0] = 0.0f;  // d_out is poisoned; zero it here (ordered before edge kernel)
        }
    }
}

__device__ __forceinline__ float pair_energy(int i, int j,
                                             const float* __restrict__ s_tab,
                                             float c0, float c1, float c2, float c3,
                                             float e0, float e1, float e2, float e3,
                                             float inv_an) {
    // two aligned 16B gathers (L2-resident working set, 1.6 MB)
    float4 pi = __ldg(&g_Rp[i]);
    float4 pj = __ldg(&g_Rp[j]);
    float dx = pj.x - pi.x;
    float dy = pj.y - pi.y;
    float dz = pj.z - pi.z;
    float dr2 = fmaf(dx, dx, fmaf(dy, dy, dz * dz));
    // dr >= R_MAX  ->  cos cutoff = 0  ->  zero contribution. Self edges masked.
    if (dr2 >= R_MAX_F * R_MAX_F || i == j) return 0.0f;
    float dr = fmaxf(sqrtf(dr2), 0.02f);
    float cut = 0.5f * (cospif(dr * (1.0f / R_MAX_F)) + 1.0f);
    int zi = (int)pi.w;
    int zj = (int)pj.w;
    float dist = dr * (s_tab[zi] + s_tab[zj]) * inv_an;
    float f = c0 * expf(-e0 * dist)
            + c1 * expf(-e1 * dist)
            + c2 * expf(-e2 * dist)
            + c3 * expf(-e3 * dist);
    return pi.w * pj.w * f * cut / dr;
}

__global__ void __launch_bounds__(256) edge_kernel(const int* __restrict__ idx,
                                                   float* __restrict__ out,
                                                   int E) {
    __shared__ float s_tab[64];
    __shared__ float s_red[8];
    if (threadIdx.x < 64) s_tab[threadIdx.x] = g_tab[threadIdx.x];

    float c0 = g_par[0], c1 = g_par[1], c2 = g_par[2], c3 = g_par[3];
    float e0 = g_par[4], e1 = g_par[5], e2 = g_par[6], e3 = g_par[7];
    float inv_an = g_par[8], pref = g_par[9];
    __syncthreads();

    const int4* ii = reinterpret_cast<const int4*>(idx);       // idx_i row
    const int4* jj = reinterpret_cast<const int4*>(idx + E);   // idx_j row
    const int E4 = E >> 2;

    float acc = 0.0f;
    for (int t = blockIdx.x * blockDim.x + threadIdx.x; t < E4;
         t += gridDim.x * blockDim.x) {
        int4 a = __ldg(ii + t);
        int4 b = __ldg(jj + t);
        acc += pair_energy(a.x, b.x, s_tab, c0, c1, c2, c3, e0, e1, e2, e3, inv_an);
        acc += pair_energy(a.y, b.y, s_tab, c0, c1, c2, c3, e0, e1, e2, e3, inv_an);
        acc += pair_energy(a.z, b.z, s_tab, c0, c1, c2, c3, e0, e1, e2, e3, inv_an);
        acc += pair_energy(a.w, b.w, s_tab, c0, c1, c2, c3, e0, e1, e2, e3, inv_an);
    }
    // scalar tail (E % 4 != 0) handled by global thread 0
    if (blockIdx.x == 0 && threadIdx.x == 0) {
        for (int t = E4 << 2; t < E; t++) {
            acc += pair_energy(idx[t], idx[E + t], s_tab,
                               c0, c1, c2, c3, e0, e1, e2, e3, inv_an);
        }
    }

    // warp reduce
    #pragma unroll
    for (int off = 16; off > 0; off >>= 1)
        acc += __shfl_xor_sync(0xFFFFFFFFu, acc, off);

    int warp = threadIdx.x >> 5;
    int lane = threadIdx.x & 31;
    if (lane == 0) s_red[warp] = acc;
    __syncthreads();
    if (warp == 0) {
        float v = (lane < (blockDim.x >> 5)) ? s_red[lane] : 0.0f;
        #pragma unroll
        for (int off = 4; off > 0; off >>= 1)
            v += __shfl_xor_sync(0xFFFFFFFFu, v, off);
        if (lane == 0 && v != 0.0f) atomicAdd(out, v * pref);
    }
}

extern "C" void kernel_launch(void* const* d_in, const int* in_sizes, int n_in,
                              void* d_out, int out_size) {
    const float* R         = (const float*)d_in[0];
    const int*   Z         = (const int*)  d_in[1];
    const int*   idx       = (const int*)  d_in[2];
    // d_in[3] box, d_in[4] offsets: unused (free-space displacement)
    const float* a_exp     = (const float*)d_in[5];
    const float* a_num     = (const float*)d_in[6];
    const float* coef      = (const float*)d_in[7];
    const float* expo      = (const float*)d_in[8];
    const float* rep_scale = (const float*)d_in[9];
    float* out = (float*)d_out;

    int n_atoms = in_sizes[1];           // 100000
    int E = in_sizes[2] / 2;             // 6400000

    int pro_blocks = (n_atoms + 255) / 256;
    prologue_kernel<<<pro_blocks, 256>>>(R, Z, a_exp, a_num, coef, expo,
                                         rep_scale, out, n_atoms);

    int E4 = E >> 2;
    int blocks = (E4 + 255) / 256;       // 6250 for E=6.4M
    edge_kernel<<<blocks, 256>>>(idx, out, E);
}